// round 11
// baseline (speedup 1.0000x reference)
#include <cuda_runtime.h>
#include <cstdint>

// out[4096,2048] = x[4096,2048] @ W[2048,2048]^T + bias   (fp32 in/out)
// Phase 1: pre-round x,W to tf32 (stored fp32) into device-global scratch.
// Phase 2: tf32 mma.sync.m16n8k8 GEMM (R5 configuration — best measured):
// BM=BN=128, BK=32, 256 threads (warp tile 64x32), 3-stage cp.async,
// SW128 swizzle, ldmatrix-b16 fragment loads, 2 CTAs/SM.

namespace {

constexpr int Mdim = 4096;
constexpr int Ndim = 2048;
constexpr int Kdim = 2048;

constexpr int BM = 128;
constexpr int BN = 128;
constexpr int BK = 32;                    // 32 f32 = 128 B rows (SW128 atom)
constexpr int KT = Kdim / BK;             // 64 k-tiles
constexpr int STAGES = 3;

constexpr uint32_t A_BYTES = BM * BK * 4;
constexpr uint32_t B_BYTES = BN * BK * 4;
constexpr uint32_t STAGE_BYTES = A_BYTES + B_BYTES;   // 32768
constexpr uint32_t SMEM_TOTAL = STAGES * STAGE_BYTES; // 98304

constexpr int THREADS = 256;

// tf32-rounded copies of the inputs (BSS scratch; allowed per harness rules)
__device__ float g_xa[(size_t)Mdim * Kdim];   // 32 MB
__device__ float g_wb[(size_t)Ndim * Kdim];   // 16 MB

__device__ __forceinline__ uint32_t smem_u32(const void* p) {
    return (uint32_t)__cvta_generic_to_shared(p);
}
__device__ __forceinline__ uint32_t sw128(uint32_t off) {
    return off ^ ((off >> 3) & 0x70);
}
__device__ __forceinline__ void cp_async16(uint32_t dst, const void* src) {
    asm volatile("cp.async.cg.shared.global [%0], [%1], 16;"
                 :: "r"(dst), "l"(src) : "memory");
}
#define CP_COMMIT()  asm volatile("cp.async.commit_group;" ::: "memory")
#define CP_WAIT(n)   asm volatile("cp.async.wait_group %0;" :: "n"(n) : "memory")

__device__ __forceinline__ void ldsm_x4(uint32_t r[4], uint32_t addr) {
    asm volatile("ldmatrix.sync.aligned.m8n8.x4.shared.b16 {%0,%1,%2,%3}, [%4];"
                 : "=r"(r[0]), "=r"(r[1]), "=r"(r[2]), "=r"(r[3]) : "r"(addr));
}
__device__ __forceinline__ uint32_t cvt_tf32(uint32_t x) {
    uint32_t y;
    asm volatile("cvt.rna.tf32.f32 %0, %1;" : "=r"(y) : "r"(x));
    return y;
}
__device__ __forceinline__ void mma_tf32(float d[4], const uint32_t a[4],
                                         uint32_t b0, uint32_t b1) {
    asm volatile(
        "mma.sync.aligned.m16n8k8.row.col.f32.tf32.tf32.f32 "
        "{%0,%1,%2,%3}, {%4,%5,%6,%7}, {%8,%9}, {%0,%1,%2,%3};"
        : "+f"(d[0]), "+f"(d[1]), "+f"(d[2]), "+f"(d[3])
        : "r"(a[0]), "r"(a[1]), "r"(a[2]), "r"(a[3]), "r"(b0), "r"(b1));
}

// ---- phase 1: round to tf32 once, store as fp32 ----
__global__ __launch_bounds__(256)
void cvt_pass(const float4* __restrict__ sx, const float4* __restrict__ sw)
{
    constexpr int NX4 = Mdim * Kdim / 4;   // 2M float4
    constexpr int NW4 = Ndim * Kdim / 4;   // 1M float4
    float4* __restrict__ dx = (float4*)g_xa;
    float4* __restrict__ dw = (float4*)g_wb;

    const int stride = gridDim.x * blockDim.x;
    const int t0 = blockIdx.x * blockDim.x + threadIdx.x;

    for (int i = t0; i < NX4; i += stride) {
        float4 v = sx[i];
        uint4 o;
        o.x = cvt_tf32(__float_as_uint(v.x));
        o.y = cvt_tf32(__float_as_uint(v.y));
        o.z = cvt_tf32(__float_as_uint(v.z));
        o.w = cvt_tf32(__float_as_uint(v.w));
        *(uint4*)&dx[i] = o;
    }
    for (int i = t0; i < NW4; i += stride) {
        float4 v = sw[i];
        uint4 o;
        o.x = cvt_tf32(__float_as_uint(v.x));
        o.y = cvt_tf32(__float_as_uint(v.y));
        o.z = cvt_tf32(__float_as_uint(v.z));
        o.w = cvt_tf32(__float_as_uint(v.w));
        *(uint4*)&dw[i] = o;
    }
}

// ---- phase 2: GEMM ----
__global__ __launch_bounds__(THREADS, 2)
void tf32_mma_gemm(const float* __restrict__ bias, float* __restrict__ C)
{
    extern __shared__ char smem[];
    const uint32_t sb = smem_u32(smem);

    const float* __restrict__ A = g_xa;
    const float* __restrict__ W = g_wb;

    const int tid  = threadIdx.x;
    const int lane = tid & 31;
    const int wid  = tid >> 5;
    const int warp_m = wid >> 2;   // 0..1  -> 64 rows
    const int warp_n = wid & 3;    // 0..3  -> 32 cols

    const int bm = blockIdx.y * BM;
    const int bn = blockIdx.x * BN;

    // cp.async offsets: 4 x 16B chunks per thread per operand tile
    uint32_t a_go[4], a_so[4];
    #pragma unroll
    for (int t = 0; t < 4; t++) {
        int idx = t * THREADS + tid;
        int r = idx >> 3, c = idx & 7;
        a_go[t] = (uint32_t)(r * (Kdim * 4) + c * 16);
        a_so[t] = sw128((uint32_t)(r * 128 + c * 16));
    }
    const char* Abase = (const char*)(A + (size_t)bm * Kdim);
    const char* Bbase = (const char*)(W + (size_t)bn * Kdim);

    auto load_tile = [&](int stage, int kt) {
        const uint32_t sA = sb + (uint32_t)stage * STAGE_BYTES;
        const uint32_t sB = sA + A_BYTES;
        const char* Ak = Abase + (uint32_t)kt * (BK * 4);
        const char* Bk = Bbase + (uint32_t)kt * (BK * 4);
        #pragma unroll
        for (int t = 0; t < 4; t++) cp_async16(sA + a_so[t], Ak + a_go[t]);
        #pragma unroll
        for (int t = 0; t < 4; t++) cp_async16(sB + a_so[t], Bk + a_go[t]);
    };

    // ldmatrix per-lane base offsets (mapping validated R3-R10)
    const int lr  = lane & 7;
    const int g1  = (lane >> 3) & 1;
    const int hi  = lane >> 4;
    const uint32_t a_boff = (uint32_t)((warp_m * 64 + g1 * 8 + lr) * 128 + hi * 16);
    const uint32_t b_boff = (uint32_t)((warp_n * 32 + hi * 8 + lr) * 128 + g1 * 16);

    float d[4][4][4];
    #pragma unroll
    for (int mi = 0; mi < 4; mi++)
        #pragma unroll
        for (int ni = 0; ni < 4; ni++)
            #pragma unroll
            for (int r = 0; r < 4; r++) d[mi][ni][r] = 0.0f;

    // hoist loop-invariant bias values (off the epilogue critical path)
    float2 bv[4];
    #pragma unroll
    for (int ni = 0; ni < 4; ni++)
        bv[ni] = *(const float2*)(bias + bn + warp_n * 32 + ni * 8 + (lane & 3) * 2);

    #pragma unroll
    for (int p = 0; p < STAGES - 1; p++) { load_tile(p, p); CP_COMMIT(); }

    int cs = 0;
    for (int kt = 0; kt < KT; kt++) {
        CP_WAIT(STAGES - 2);
        __syncthreads();

        {
            int lkt = kt + STAGES - 1;
            int lst = cs - 1; if (lst < 0) lst += STAGES;
            if (lkt < KT) load_tile(lst, lkt);
            CP_COMMIT();
        }

        const uint32_t sA = sb + (uint32_t)cs * STAGE_BYTES;
        const uint32_t sB = sA + A_BYTES;

        #pragma unroll
        for (int ks = 0; ks < 4; ks++) {          // 4 x k=8 per 32-k tile
            uint32_t a[4][4];
            #pragma unroll
            for (int mi = 0; mi < 4; mi++)
                ldsm_x4(a[mi], sA + sw128(a_boff + mi * 2048 + ks * 32));
            uint32_t b[2][4];
            #pragma unroll
            for (int ns = 0; ns < 2; ns++)
                ldsm_x4(b[ns], sB + sw128(b_boff + ns * 2048 + ks * 32));
            #pragma unroll
            for (int mi = 0; mi < 4; mi++)
                #pragma unroll
                for (int ni = 0; ni < 4; ni++)
                    mma_tf32(d[mi][ni], a[mi],
                             b[ni >> 1][(ni & 1) * 2],
                             b[ni >> 1][(ni & 1) * 2 + 1]);
        }

        cs = (cs + 1 < STAGES) ? cs + 1 : 0;
    }

    // epilogue: bias + float2 stores (4 adjacent lanes = one 32B sector)
    #pragma unroll
    for (int ni = 0; ni < 4; ni++) {
        const int col = bn + warp_n * 32 + ni * 8 + (lane & 3) * 2;
        #pragma unroll
        for (int mi = 0; mi < 4; mi++) {
            const int row0 = bm + warp_m * 64 + mi * 16 + (lane >> 2);
            float2 v0 = { d[mi][ni][0] + bv[ni].x, d[mi][ni][1] + bv[ni].y };
            float2 v1 = { d[mi][ni][2] + bv[ni].x, d[mi][ni][3] + bv[ni].y };
            *(float2*)(C + (size_t)row0 * Ndim + col) = v0;
            *(float2*)(C + (size_t)(row0 + 8) * Ndim + col) = v1;
        }
    }
}

} // namespace

extern "C" void kernel_launch(void* const* d_in, const int* in_sizes, int n_in,
                              void* d_out, int out_size)
{
    const float* x    = (const float*)d_in[0];
    const float* w    = (const float*)d_in[1];
    const float* bias = (const float*)d_in[2];
    float* out        = (float*)d_out;

    cudaFuncSetAttribute(tf32_mma_gemm,
                         cudaFuncAttributeMaxDynamicSharedMemorySize, SMEM_TOTAL);

    // Phase 1: one-time-per-call tf32 rounding of x and W into scratch.
    // 4736 blocks = 32 per SM for full-chip coverage of the streaming pass.
    cvt_pass<<<4736, 256>>>((const float4*)x, (const float4*)w);

    // Phase 2: GEMM (reads scratch, writes out). Same stream -> ordered.
    dim3 grid(Ndim / BN, Mdim / BM);   // (16, 32) = 512 CTAs
    tf32_mma_gemm<<<grid, THREADS, SMEM_TOTAL>>>(bias, out);
}

// round 12
// speedup vs baseline: 1.0631x; 1.0631x over previous
#include <cuda_runtime.h>
#include <cstdint>

// out[4096,2048] = x[4096,2048] @ W[2048,2048]^T + bias   (fp32 in/out)
// Phase 1: pre-round x,W to tf32 (stored fp32) into device-global scratch.
// Phase 2: tf32 mma.sync.m16n8k8 GEMM, 3-stage cp.async pipeline, SW128
// swizzle, ldmatrix-b16 fragment loads, 2 CTAs/SM (96KB smem, <=128 regs).
// Exact R5 configuration — best measured (189.2us). Bias loads stay in the
// epilogue: hoisting them costs ~12us by pinning 8 regs across the mainloop
// at the 128-reg occupancy cap (measured R9/R10/R11).

namespace {

constexpr int Mdim = 4096;
constexpr int Ndim = 2048;
constexpr int Kdim = 2048;

constexpr int BM = 128;
constexpr int BN = 128;
constexpr int BK = 32;                    // 32 f32 = 128 B rows (SW128 atom)
constexpr int KT = Kdim / BK;             // 64 k-tiles
constexpr int STAGES = 3;

constexpr uint32_t A_BYTES = BM * BK * 4;
constexpr uint32_t B_BYTES = BN * BK * 4;
constexpr uint32_t STAGE_BYTES = A_BYTES + B_BYTES;   // 32768
constexpr uint32_t SMEM_TOTAL = STAGES * STAGE_BYTES; // 98304

constexpr int THREADS = 256;

// tf32-rounded copies of the inputs (BSS scratch; allowed per harness rules)
__device__ float g_xa[(size_t)Mdim * Kdim];   // 32 MB
__device__ float g_wb[(size_t)Ndim * Kdim];   // 16 MB

__device__ __forceinline__ uint32_t smem_u32(const void* p) {
    return (uint32_t)__cvta_generic_to_shared(p);
}
__device__ __forceinline__ uint32_t sw128(uint32_t off) {
    return off ^ ((off >> 3) & 0x70);
}
__device__ __forceinline__ void cp_async16(uint32_t dst, const void* src) {
    asm volatile("cp.async.cg.shared.global [%0], [%1], 16;"
                 :: "r"(dst), "l"(src) : "memory");
}
#define CP_COMMIT()  asm volatile("cp.async.commit_group;" ::: "memory")
#define CP_WAIT(n)   asm volatile("cp.async.wait_group %0;" :: "n"(n) : "memory")

__device__ __forceinline__ void ldsm_x4(uint32_t r[4], uint32_t addr) {
    asm volatile("ldmatrix.sync.aligned.m8n8.x4.shared.b16 {%0,%1,%2,%3}, [%4];"
                 : "=r"(r[0]), "=r"(r[1]), "=r"(r[2]), "=r"(r[3]) : "r"(addr));
}
__device__ __forceinline__ uint32_t cvt_tf32(uint32_t x) {
    uint32_t y;
    asm volatile("cvt.rna.tf32.f32 %0, %1;" : "=r"(y) : "r"(x));
    return y;
}
__device__ __forceinline__ void mma_tf32(float d[4], const uint32_t a[4],
                                         uint32_t b0, uint32_t b1) {
    asm volatile(
        "mma.sync.aligned.m16n8k8.row.col.f32.tf32.tf32.f32 "
        "{%0,%1,%2,%3}, {%4,%5,%6,%7}, {%8,%9}, {%0,%1,%2,%3};"
        : "+f"(d[0]), "+f"(d[1]), "+f"(d[2]), "+f"(d[3])
        : "r"(a[0]), "r"(a[1]), "r"(a[2]), "r"(a[3]), "r"(b0), "r"(b1));
}

// ---- phase 1: round to tf32 once, store as fp32 ----
__global__ __launch_bounds__(256)
void cvt_pass(const float4* __restrict__ sx, const float4* __restrict__ sw)
{
    constexpr int NX4 = Mdim * Kdim / 4;
    constexpr int NW4 = Ndim * Kdim / 4;
    float4* __restrict__ dx = (float4*)g_xa;
    float4* __restrict__ dw = (float4*)g_wb;

    const int stride = gridDim.x * blockDim.x;
    for (int i = blockIdx.x * blockDim.x + threadIdx.x; i < NX4; i += stride) {
        float4 v = sx[i];
        uint4 o;
        o.x = cvt_tf32(__float_as_uint(v.x));
        o.y = cvt_tf32(__float_as_uint(v.y));
        o.z = cvt_tf32(__float_as_uint(v.z));
        o.w = cvt_tf32(__float_as_uint(v.w));
        *(uint4*)&dx[i] = o;
    }
    for (int i = blockIdx.x * blockDim.x + threadIdx.x; i < NW4; i += stride) {
        float4 v = sw[i];
        uint4 o;
        o.x = cvt_tf32(__float_as_uint(v.x));
        o.y = cvt_tf32(__float_as_uint(v.y));
        o.z = cvt_tf32(__float_as_uint(v.z));
        o.w = cvt_tf32(__float_as_uint(v.w));
        *(uint4*)&dw[i] = o;
    }
}

// ---- phase 2: GEMM ----
__global__ __launch_bounds__(THREADS, 2)
void tf32_mma_gemm(const float* __restrict__ bias, float* __restrict__ C)
{
    extern __shared__ char smem[];
    const uint32_t sb = smem_u32(smem);

    const float* __restrict__ A = g_xa;
    const float* __restrict__ W = g_wb;

    const int tid  = threadIdx.x;
    const int lane = tid & 31;
    const int wid  = tid >> 5;
    const int warp_m = wid >> 2;   // 0..1  -> 64 rows
    const int warp_n = wid & 3;    // 0..3  -> 32 cols

    const int bm = blockIdx.y * BM;
    const int bn = blockIdx.x * BN;

    // cp.async offsets: 4 x 16B chunks per thread per operand tile
    uint32_t a_go[4], a_so[4];
    #pragma unroll
    for (int t = 0; t < 4; t++) {
        int idx = t * THREADS + tid;
        int r = idx >> 3, c = idx & 7;
        a_go[t] = (uint32_t)(r * (Kdim * 4) + c * 16);
        a_so[t] = sw128((uint32_t)(r * 128 + c * 16));
    }
    const char* Abase = (const char*)(A + (size_t)bm * Kdim);
    const char* Bbase = (const char*)(W + (size_t)bn * Kdim);

    auto load_tile = [&](int stage, int kt) {
        const uint32_t sA = sb + (uint32_t)stage * STAGE_BYTES;
        const uint32_t sB = sA + A_BYTES;
        const char* Ak = Abase + (uint32_t)kt * (BK * 4);
        const char* Bk = Bbase + (uint32_t)kt * (BK * 4);
        #pragma unroll
        for (int t = 0; t < 4; t++) cp_async16(sA + a_so[t], Ak + a_go[t]);
        #pragma unroll
        for (int t = 0; t < 4; t++) cp_async16(sB + a_so[t], Bk + a_go[t]);
    };

    // ldmatrix per-lane base offsets (mapping validated R3-R11)
    const int lr  = lane & 7;
    const int g1  = (lane >> 3) & 1;
    const int hi  = lane >> 4;
    const uint32_t a_boff = (uint32_t)((warp_m * 64 + g1 * 8 + lr) * 128 + hi * 16);
    const uint32_t b_boff = (uint32_t)((warp_n * 32 + hi * 8 + lr) * 128 + g1 * 16);

    float d[4][4][4];
    #pragma unroll
    for (int mi = 0; mi < 4; mi++)
        #pragma unroll
        for (int ni = 0; ni < 4; ni++)
            #pragma unroll
            for (int r = 0; r < 4; r++) d[mi][ni][r] = 0.0f;

    #pragma unroll
    for (int p = 0; p < STAGES - 1; p++) { load_tile(p, p); CP_COMMIT(); }

    int cs = 0;
    for (int kt = 0; kt < KT; kt++) {
        CP_WAIT(STAGES - 2);
        __syncthreads();

        {
            int lkt = kt + STAGES - 1;
            int lst = cs - 1; if (lst < 0) lst += STAGES;
            if (lkt < KT) load_tile(lst, lkt);
            CP_COMMIT();
        }

        const uint32_t sA = sb + (uint32_t)cs * STAGE_BYTES;
        const uint32_t sB = sA + A_BYTES;

        #pragma unroll
        for (int ks = 0; ks < 4; ks++) {          // 4 x k=8 per 32-k tile
            uint32_t a[4][4];
            #pragma unroll
            for (int mi = 0; mi < 4; mi++)
                ldsm_x4(a[mi], sA + sw128(a_boff + mi * 2048 + ks * 32));
            uint32_t b[2][4];
            #pragma unroll
            for (int ns = 0; ns < 2; ns++)
                ldsm_x4(b[ns], sB + sw128(b_boff + ns * 2048 + ks * 32));
            #pragma unroll
            for (int mi = 0; mi < 4; mi++)
                #pragma unroll
                for (int ni = 0; ni < 4; ni++)
                    mma_tf32(d[mi][ni], a[mi],
                             b[ni >> 1][(ni & 1) * 2],
                             b[ni >> 1][(ni & 1) * 2 + 1]);
        }

        cs = (cs + 1 < STAGES) ? cs + 1 : 0;
    }

    // epilogue: bias + float2 stores (4 adjacent lanes = one 32B sector).
    // Bias is loaded HERE, after the accumulators' register pressure drops.
    #pragma unroll
    for (int ni = 0; ni < 4; ni++) {
        const int col = bn + warp_n * 32 + ni * 8 + (lane & 3) * 2;
        const float2 bv = *(const float2*)(bias + col);
        #pragma unroll
        for (int mi = 0; mi < 4; mi++) {
            const int row0 = bm + warp_m * 64 + mi * 16 + (lane >> 2);
            float2 v0 = { d[mi][ni][0] + bv.x, d[mi][ni][1] + bv.y };
            float2 v1 = { d[mi][ni][2] + bv.x, d[mi][ni][3] + bv.y };
            *(float2*)(C + (size_t)row0 * Ndim + col) = v0;
            *(float2*)(C + (size_t)(row0 + 8) * Ndim + col) = v1;
        }
    }
}

} // namespace

extern "C" void kernel_launch(void* const* d_in, const int* in_sizes, int n_in,
                              void* d_out, int out_size)
{
    const float* x    = (const float*)d_in[0];
    const float* w    = (const float*)d_in[1];
    const float* bias = (const float*)d_in[2];
    float* out        = (float*)d_out;

    cudaFuncSetAttribute(tf32_mma_gemm,
                         cudaFuncAttributeMaxDynamicSharedMemorySize, SMEM_TOTAL);

    // Phase 1: one-time-per-call tf32 rounding of x and W into scratch.
    cvt_pass<<<2048, 256>>>((const float4*)x, (const float4*)w);

    // Phase 2: GEMM (reads scratch, writes out). Same stream -> ordered.
    dim3 grid(Ndim / BN, Mdim / BM);   // (16, 32) = 512 CTAs
    tf32_mma_gemm<<<grid, THREADS, SMEM_TOTAL>>>(bias, out);
}

// round 17
// speedup vs baseline: 1.1280x; 1.0610x over previous
#include <cuda_runtime.h>
#include <cstdint>

// out[4096,2048] = x[4096,2048] @ W[2048,2048]^T + bias   (fp32 in/out)
// Phase 1: RNA-round W to tf32 into device-global scratch, pre-scaled by
// (1 + 3.52e-4) to cancel the bias of feeding RAW fp32 x into the tf32 mma
// (HW truncates x's low 13 mantissa bits; compensation makes the error
// zero-mean; residual noise ~= RNA noise — validated rel_err 3.0e-4 in R9).
// Phase 2: tf32 mma.sync.m16n8k8 GEMM — R12/R5 configuration verbatim
// (best measured: GEMM 173.7us): BM=BN=128, BK=32, 256 threads (warp tile
// 64x32), 3-stage cp.async, SW128 swizzle, 2 CTAs/SM, bias loaded in the
// epilogue (hoisting it pins 8 regs across the mainloop and costs ~12us).
// A is read directly from d_in[0]; only W comes from scratch.
// (Third submission: R13/R15 attempts died to broker infra faults before
// the kernel ran — "system not yet initialized", then container failure.)

namespace {

constexpr int Mdim = 4096;
constexpr int Ndim = 2048;
constexpr int Kdim = 2048;

constexpr int BM = 128;
constexpr int BN = 128;
constexpr int BK = 32;                    // 32 f32 = 128 B rows (SW128 atom)
constexpr int KT = Kdim / BK;             // 64 k-tiles
constexpr int STAGES = 3;

constexpr uint32_t A_BYTES = BM * BK * 4;
constexpr uint32_t B_BYTES = BN * BK * 4;
constexpr uint32_t STAGE_BYTES = A_BYTES + B_BYTES;   // 32768
constexpr uint32_t SMEM_TOTAL = STAGES * STAGE_BYTES; // 98304

constexpr int THREADS = 256;

// Bias compensation for x-truncation: E[relative truncation] = 2^-11 * 0.721
constexpr float WSCALE = 1.000352f;

// tf32-rounded, bias-compensated copy of W (BSS scratch; allowed)
__device__ float g_wb[(size_t)Ndim * Kdim];   // 16 MB

__device__ __forceinline__ uint32_t smem_u32(const void* p) {
    return (uint32_t)__cvta_generic_to_shared(p);
}
__device__ __forceinline__ uint32_t sw128(uint32_t off) {
    return off ^ ((off >> 3) & 0x70);
}
__device__ __forceinline__ void cp_async16(uint32_t dst, const void* src) {
    asm volatile("cp.async.cg.shared.global [%0], [%1], 16;"
                 :: "r"(dst), "l"(src) : "memory");
}
#define CP_COMMIT()  asm volatile("cp.async.commit_group;" ::: "memory")
#define CP_WAIT(n)   asm volatile("cp.async.wait_group %0;" :: "n"(n) : "memory")

__device__ __forceinline__ void ldsm_x4(uint32_t r[4], uint32_t addr) {
    asm volatile("ldmatrix.sync.aligned.m8n8.x4.shared.b16 {%0,%1,%2,%3}, [%4];"
                 : "=r"(r[0]), "=r"(r[1]), "=r"(r[2]), "=r"(r[3]) : "r"(addr));
}
__device__ __forceinline__ float cvt_tf32_f(float x) {
    uint32_t y;
    asm volatile("cvt.rna.tf32.f32 %0, %1;" : "=r"(y) : "r"(__float_as_uint(x)));
    return __uint_as_float(y);
}
__device__ __forceinline__ void mma_tf32(float d[4], const uint32_t a[4],
                                         uint32_t b0, uint32_t b1) {
    asm volatile(
        "mma.sync.aligned.m16n8k8.row.col.f32.tf32.tf32.f32 "
        "{%0,%1,%2,%3}, {%4,%5,%6,%7}, {%8,%9}, {%0,%1,%2,%3};"
        : "+f"(d[0]), "+f"(d[1]), "+f"(d[2]), "+f"(d[3])
        : "r"(a[0]), "r"(a[1]), "r"(a[2]), "r"(a[3]), "r"(b0), "r"(b1));
}

// ---- phase 1: compensate + RNA-round W once (W only; x stays raw) ----
__global__ __launch_bounds__(256)
void cvt_w_pass(const float4* __restrict__ sw)
{
    constexpr int NW4 = Ndim * Kdim / 4;   // 1M float4
    float4* __restrict__ dw = (float4*)g_wb;

    const int stride = gridDim.x * blockDim.x;
    for (int i = blockIdx.x * blockDim.x + threadIdx.x; i < NW4; i += stride) {
        float4 v = sw[i];
        float4 o;
        o.x = cvt_tf32_f(v.x * WSCALE);
        o.y = cvt_tf32_f(v.y * WSCALE);
        o.z = cvt_tf32_f(v.z * WSCALE);
        o.w = cvt_tf32_f(v.w * WSCALE);
        dw[i] = o;
    }
}

// ---- phase 2: GEMM (A = raw x from d_in, HW-truncated; W = scratch) ----
__global__ __launch_bounds__(THREADS, 2)
void tf32_mma_gemm(const float* __restrict__ A,
                   const float* __restrict__ bias, float* __restrict__ C)
{
    extern __shared__ char smem[];
    const uint32_t sb = smem_u32(smem);

    const float* __restrict__ W = g_wb;

    const int tid  = threadIdx.x;
    const int lane = tid & 31;
    const int wid  = tid >> 5;
    const int warp_m = wid >> 2;   // 0..1  -> 64 rows
    const int warp_n = wid & 3;    // 0..3  -> 32 cols

    const int bm = blockIdx.y * BM;
    const int bn = blockIdx.x * BN;

    // cp.async offsets: 4 x 16B chunks per thread per operand tile
    uint32_t a_go[4], a_so[4];
    #pragma unroll
    for (int t = 0; t < 4; t++) {
        int idx = t * THREADS + tid;
        int r = idx >> 3, c = idx & 7;
        a_go[t] = (uint32_t)(r * (Kdim * 4) + c * 16);
        a_so[t] = sw128((uint32_t)(r * 128 + c * 16));
    }
    const char* Abase = (const char*)(A + (size_t)bm * Kdim);
    const char* Bbase = (const char*)(W + (size_t)bn * Kdim);

    auto load_tile = [&](int stage, int kt) {
        const uint32_t sA = sb + (uint32_t)stage * STAGE_BYTES;
        const uint32_t sB = sA + A_BYTES;
        const char* Ak = Abase + (uint32_t)kt * (BK * 4);
        const char* Bk = Bbase + (uint32_t)kt * (BK * 4);
        #pragma unroll
        for (int t = 0; t < 4; t++) cp_async16(sA + a_so[t], Ak + a_go[t]);
        #pragma unroll
        for (int t = 0; t < 4; t++) cp_async16(sB + a_so[t], Bk + a_go[t]);
    };

    // ldmatrix per-lane base offsets (mapping validated R3-R12)
    const int lr  = lane & 7;
    const int g1  = (lane >> 3) & 1;
    const int hi  = lane >> 4;
    const uint32_t a_boff = (uint32_t)((warp_m * 64 + g1 * 8 + lr) * 128 + hi * 16);
    const uint32_t b_boff = (uint32_t)((warp_n * 32 + hi * 8 + lr) * 128 + g1 * 16);

    float d[4][4][4];
    #pragma unroll
    for (int mi = 0; mi < 4; mi++)
        #pragma unroll
        for (int ni = 0; ni < 4; ni++)
            #pragma unroll
            for (int r = 0; r < 4; r++) d[mi][ni][r] = 0.0f;

    #pragma unroll
    for (int p = 0; p < STAGES - 1; p++) { load_tile(p, p); CP_COMMIT(); }

    int cs = 0;
    for (int kt = 0; kt < KT; kt++) {
        CP_WAIT(STAGES - 2);
        __syncthreads();

        {
            int lkt = kt + STAGES - 1;
            int lst = cs - 1; if (lst < 0) lst += STAGES;
            if (lkt < KT) load_tile(lst, lkt);
            CP_COMMIT();
        }

        const uint32_t sA = sb + (uint32_t)cs * STAGE_BYTES;
        const uint32_t sB = sA + A_BYTES;

        #pragma unroll
        for (int ks = 0; ks < 4; ks++) {          // 4 x k=8 per 32-k tile
            uint32_t a[4][4];
            #pragma unroll
            for (int mi = 0; mi < 4; mi++)
                ldsm_x4(a[mi], sA + sw128(a_boff + mi * 2048 + ks * 32));
            uint32_t b[2][4];
            #pragma unroll
            for (int ns = 0; ns < 2; ns++)
                ldsm_x4(b[ns], sB + sw128(b_boff + ns * 2048 + ks * 32));
            #pragma unroll
            for (int mi = 0; mi < 4; mi++)
                #pragma unroll
                for (int ni = 0; ni < 4; ni++)
                    mma_tf32(d[mi][ni], a[mi],
                             b[ni >> 1][(ni & 1) * 2],
                             b[ni >> 1][(ni & 1) * 2 + 1]);
        }

        cs = (cs + 1 < STAGES) ? cs + 1 : 0;
    }

    // epilogue: bias + float2 stores (4 adjacent lanes = one 32B sector).
    // Bias is loaded HERE, after the accumulators' register pressure drops.
    #pragma unroll
    for (int ni = 0; ni < 4; ni++) {
        const int col = bn + warp_n * 32 + ni * 8 + (lane & 3) * 2;
        const float2 bv = *(const float2*)(bias + col);
        #pragma unroll
        for (int mi = 0; mi < 4; mi++) {
            const int row0 = bm + warp_m * 64 + mi * 16 + (lane >> 2);
            float2 v0 = { d[mi][ni][0] + bv.x, d[mi][ni][1] + bv.y };
            float2 v1 = { d[mi][ni][2] + bv.x, d[mi][ni][3] + bv.y };
            *(float2*)(C + (size_t)row0 * Ndim + col) = v0;
            *(float2*)(C + (size_t)(row0 + 8) * Ndim + col) = v1;
        }
    }
}

} // namespace

extern "C" void kernel_launch(void* const* d_in, const int* in_sizes, int n_in,
                              void* d_out, int out_size)
{
    const float* x    = (const float*)d_in[0];
    const float* w    = (const float*)d_in[1];
    const float* bias = (const float*)d_in[2];
    float* out        = (float*)d_out;

    cudaFuncSetAttribute(tf32_mma_gemm,
                         cudaFuncAttributeMaxDynamicSharedMemorySize, SMEM_TOTAL);

    // Phase 1: compensate + RNA-round W only (x is HW-truncated in the mma).
    cvt_w_pass<<<1024, 256>>>((const float4*)w);

    // Phase 2: GEMM (reads x directly + W scratch). Same stream -> ordered.
    dim3 grid(Ndim / BN, Mdim / BM);   // (16, 32) = 512 CTAs
    tf32_mma_gemm<<<grid, THREADS, SMEM_TOTAL>>>(x, bias, out);
}